// round 8
// baseline (speedup 1.0000x reference)
#include <cuda_runtime.h>
#include <cuda_bf16.h>
#include <cstdint>

typedef unsigned long long u64;

// Problem constants
#define B 4
#define C 4
#define H 256
#define W 256
#define HW (H*W)          // 65536
#define FS 11
#define PAD 5

// Tile config
#define BW 32             // tile width (output pixels)
#define BH 8              // tile height
#define R  2              // pixels per thread along w
#define NTHREADS 128      // (BW/R) * BH = 16 * 8
#define HALO_W (BW + FS - 1)   // 42
#define HALO_H (BH + FS - 1)   // 18
#define NHALO (HALO_H * HALO_W)  // 756
#define NHIT ((NHALO + NTHREADS - 1) / NTHREADS)   // 6
#define SST 43            // shared row stride in 16B units (bank-skewed)

__device__ __forceinline__ float ex2(float s) {
    float r;
    asm("ex2.approx.f32 %0, %1;" : "=f"(r) : "f"(s));
    return r;
}
__device__ __forceinline__ u64 fma2(u64 a, u64 b, u64 c) {
    u64 d;
    asm("fma.rn.f32x2 %0, %1, %2, %3;" : "=l"(d) : "l"(a), "l"(b), "l"(c));
    return d;
}
__device__ __forceinline__ u64 mul2(u64 a, u64 b) {
    u64 d;
    asm("mul.rn.f32x2 %0, %1, %2;" : "=l"(d) : "l"(a), "l"(b));
    return d;
}
__device__ __forceinline__ u64 dup2(float e) {
    u64 d;
    asm("mov.b64 %0, {%1, %1};" : "=l"(d) : "f"(e));
    return d;
}
__device__ __forceinline__ u64 packf2(float a, float b) {
    u64 d;
    asm("mov.b64 %0, {%1, %2};" : "=l"(d) : "f"(a), "f"(b));
    return d;
}
__device__ __forceinline__ float2 unpack2(u64 v) {
    float2 f;
    asm("mov.b64 {%0, %1}, %2;" : "=f"(f.x), "=f"(f.y) : "l"(v));
    return f;
}

// Phase-split batch over NK taps of one window row:
//   A: scores (LDS + FMA only)  B: EX2 burst  C: accumulate (FMA only)
#define BATCH(KJ0, NK) do {                                               \
    ulonglong2 Xw[(NK) + 1];                                              \
    _Pragma("unroll")                                                     \
    for (int j = 0; j <= (NK); j++) Xw[j] = row[(KJ0) + j];               \
    float ee[(NK) * 2];                                                   \
    _Pragma("unroll")                                                     \
    for (int kj = 0; kj < (NK); kj++) {                                   \
        _Pragma("unroll")                                                 \
        for (int r = 0; r < R; r++) {                                     \
            ulonglong2 X = Xw[kj + r];                                    \
            u64 t = mul2(psiA[r], X.x);                                   \
            t = fma2(psiB[r], X.y, t);                                    \
            float2 f = unpack2(t);                                        \
            ee[kj * 2 + r] = f.x + f.y;                                   \
        }                                                                 \
    }                                                                     \
    _Pragma("unroll")                                                     \
    for (int q = 0; q < (NK) * 2; q++) ee[q] = ex2(ee[q]);                \
    _Pragma("unroll")                                                     \
    for (int kj = 0; kj < (NK); kj++) {                                   \
        _Pragma("unroll")                                                 \
        for (int r = 0; r < R; r++) {                                     \
            ulonglong2 X = Xw[kj + r];                                    \
            float e = ee[kj * 2 + r];                                     \
            u64 ed = dup2(e);                                             \
            sum[r] += e;                                                  \
            accA[r] = fma2(ed, X.x, accA[r]);                             \
            accB[r] = fma2(ed, X.y, accB[r]);                             \
        }                                                                 \
    }                                                                     \
} while (0)

// ---------------------------------------------------------------------------
// Single fused kernel, algebraically folded:
//   score_k = psi . x_k   with  psi = (Wp^T Wt) x_p  (pre-scaled by log2 e)
//   out     = M (sum_k att_k x_k) + x,  M = Ww Wg
// ---------------------------------------------------------------------------
__global__ __launch_bounds__(NTHREADS) void fused_kernel(
    const float* __restrict__ x,
    const float* __restrict__ Wt,
    const float* __restrict__ Wp,
    const float* __restrict__ Wg,
    const float* __restrict__ Ww,
    float* __restrict__ out)
{
    __shared__ ulonglong2 xsh[HALO_H * SST];   // x halo: (c01, c23) f32 pairs
    __shared__ float wN[16];                   // N = Wp^T Wt, scaled by log2 e
    __shared__ float wM[16];                   // M = Ww Wg

    int tid = threadIdx.x;

    int b  = blockIdx.z;
    int h0 = blockIdx.y * BH;
    int w0 = blockIdx.x * BW;
    const float* xb = x + b * (C * HW);

    // --- Small matrix products N, M (threads 0..31, one entry each) ---
    if (tid < 32) {
        int e = tid & 15;
        int i = e >> 2;       // row
        int j = e & 3;        // col
        if (tid < 16) {
            float s = Wp[i] * Wt[j];
            s = fmaf(Wp[4 + i],  Wt[4 + j],  s);
            s = fmaf(Wp[8 + i],  Wt[8 + j],  s);
            s = fmaf(Wp[12 + i], Wt[12 + j], s);
            wN[e] = s * 1.4426950408889634f;
        } else {
            float s = Ww[i*4 + 0] * Wg[j];
            s = fmaf(Ww[i*4 + 1], Wg[4 + j],  s);
            s = fmaf(Ww[i*4 + 2], Wg[8 + j],  s);
            s = fmaf(Ww[i*4 + 3], Wg[12 + j], s);
            wM[e] = s;
        }
    }

    // --- Halo: batch ALL global loads first (MLP), then all shared stores ---
    float v0[NHIT], v1[NHIT], v2[NHIT], v3[NHIT];
    #pragma unroll
    for (int it = 0; it < NHIT; it++) {
        int idx = it * NTHREADS + tid;
        v0[it] = 0.f; v1[it] = 0.f; v2[it] = 0.f; v3[it] = 0.f;
        if (idx < NHALO) {
            int i  = idx / HALO_W;
            int j  = idx - i * HALO_W;
            int gh = h0 - PAD + i;
            int gw = w0 - PAD + j;
            if ((unsigned)gh < (unsigned)H && (unsigned)gw < (unsigned)W) {
                const float* xp = xb + gh * W + gw;
                v0[it] = xp[0];
                v1[it] = xp[HW];
                v2[it] = xp[2*HW];
                v3[it] = xp[3*HW];
            }
        }
    }
    #pragma unroll
    for (int it = 0; it < NHIT; it++) {
        int idx = it * NTHREADS + tid;
        if (idx < NHALO) {
            int i  = idx / HALO_W;
            int j  = idx - i * HALO_W;
            xsh[i * SST + j] = make_ulonglong2(packf2(v0[it], v1[it]),
                                               packf2(v2[it], v3[it]));
        }
    }

    // --- Own-pixel x loads (for psi and residual) ---
    // Lane mapping: ty = lane&1 (+2 per warp), tx = (lane>>1)&15.
    // Conflict-free 8-lane LDS.128 phases given SST=43.
    int tx = (tid >> 1) & 15;
    int ty = ((tid >> 5) << 1) | (tid & 1);
    int oh = h0 + ty;
    int ow = w0 + tx * R;
    int pixbase = oh * W + ow;

    float xs[4][R];
    #pragma unroll
    for (int c = 0; c < 4; c++) {
        float2 v = *(const float2*)(xb + c * HW + pixbase);
        xs[c][0] = v.x; xs[c][1] = v.y;
    }
    __syncthreads();

    // --- psi = N x_p (per own pixel), packed as f32x2 pairs ---
    u64 psiA[R], psiB[R];
    u64 accA[R], accB[R];
    float sum[R];
    #pragma unroll
    for (int r = 0; r < R; r++) {
        float p0 = fmaf(wN[0],  xs[0][r], fmaf(wN[1],  xs[1][r], fmaf(wN[2],  xs[2][r], wN[3]  * xs[3][r])));
        float p1 = fmaf(wN[4],  xs[0][r], fmaf(wN[5],  xs[1][r], fmaf(wN[6],  xs[2][r], wN[7]  * xs[3][r])));
        float p2 = fmaf(wN[8],  xs[0][r], fmaf(wN[9],  xs[1][r], fmaf(wN[10], xs[2][r], wN[11] * xs[3][r])));
        float p3 = fmaf(wN[12], xs[0][r], fmaf(wN[13], xs[1][r], fmaf(wN[14], xs[2][r], wN[15] * xs[3][r])));
        psiA[r] = packf2(p0, p1);
        psiB[r] = packf2(p2, p3);
        accA[r] = 0ull; accB[r] = 0ull;
        sum[r] = 0.f;
    }

    int base = ty * SST + tx * R;

    // --- Main loop: per window row, 3 phase-split batches (4+4+3 taps) ---
    #pragma unroll 1
    for (int ki = 0; ki < FS; ki++) {
        const ulonglong2* row = &xsh[base + ki * SST];
        BATCH(0, 4);
        BATCH(4, 4);
        BATCH(8, 3);
    }

    // --- Epilogue: normalize, apply M, residual; float2 stores ---
    float a0[R], a1[R], a2[R], a3[R];
    #pragma unroll
    for (int r = 0; r < R; r++) {
        float inv = __frcp_rn(sum[r]);
        float2 fA = unpack2(accA[r]);
        float2 fB = unpack2(accB[r]);
        a0[r] = fA.x * inv;
        a1[r] = fA.y * inv;
        a2[r] = fB.x * inv;
        a3[r] = fB.y * inv;
    }
    float* ob = out + b * (C * HW);
    #pragma unroll
    for (int c = 0; c < C; c++) {
        float2 res;
        res.x = fmaf(wM[c*4+0], a0[0], fmaf(wM[c*4+1], a1[0], fmaf(wM[c*4+2], a2[0], wM[c*4+3] * a3[0]))) + xs[c][0];
        res.y = fmaf(wM[c*4+0], a0[1], fmaf(wM[c*4+1], a1[1], fmaf(wM[c*4+2], a2[1], wM[c*4+3] * a3[1]))) + xs[c][1];
        *(float2*)(ob + c * HW + pixbase) = res;
    }
}

// ---------------------------------------------------------------------------
extern "C" void kernel_launch(void* const* d_in, const int* in_sizes, int n_in,
                              void* d_out, int out_size)
{
    const float* x  = (const float*)d_in[0];
    const float* Wt = (const float*)d_in[1];
    const float* Wp = (const float*)d_in[2];
    const float* Wg = (const float*)d_in[3];
    const float* Ww = (const float*)d_in[4];
    float* out = (float*)d_out;

    dim3 grid(W / BW, H / BH, B);
    fused_kernel<<<grid, NTHREADS>>>(x, Wt, Wp, Wg, Ww, out);
}

// round 9
// speedup vs baseline: 1.0014x; 1.0014x over previous
#include <cuda_runtime.h>
#include <cuda_bf16.h>
#include <cstdint>

typedef unsigned long long u64;

// Problem constants
#define B 4
#define C 4
#define H 256
#define W 256
#define HW (H*W)          // 65536
#define FS 11
#define PAD 5

// Tile config
#define BW 32             // tile width (output pixels)
#define BH 8              // tile height
#define R  2              // pixels per thread along w
#define NTHREADS 128      // (BW/R) * BH = 16 * 8
#define HALO_W (BW + FS - 1)   // 42
#define HALO_H (BH + FS - 1)   // 18
#define NHALO (HALO_H * HALO_W)  // 756
#define NHIT ((NHALO + NTHREADS - 1) / NTHREADS)   // 6
#define RS 48             // plane row stride in floats (48 mod 32 = 16 -> no ty bank overlap)
#define PLANE (HALO_H * RS)    // 864 floats per channel plane

__device__ __forceinline__ float ex2(float s) {
    float r;
    asm("ex2.approx.f32 %0, %1;" : "=f"(r) : "f"(s));
    return r;
}
__device__ __forceinline__ u64 fma2(u64 a, u64 b, u64 c) {
    u64 d;
    asm("fma.rn.f32x2 %0, %1, %2, %3;" : "=l"(d) : "l"(a), "l"(b), "l"(c));
    return d;
}
__device__ __forceinline__ u64 add2(u64 a, u64 b) {
    u64 d;
    asm("add.rn.f32x2 %0, %1, %2;" : "=l"(d) : "l"(a), "l"(b));
    return d;
}
__device__ __forceinline__ u64 mul2(u64 a, u64 b) {
    u64 d;
    asm("mul.rn.f32x2 %0, %1, %2;" : "=l"(d) : "l"(a), "l"(b));
    return d;
}
__device__ __forceinline__ u64 packf2(float a, float b) {
    u64 d;
    asm("mov.b64 %0, {%1, %2};" : "=l"(d) : "f"(a), "f"(b));
    return d;
}
__device__ __forceinline__ float2 unpack2(u64 v) {
    float2 f;
    asm("mov.b64 {%0, %1}, %2;" : "=f"(f.x), "=f"(f.y) : "l"(v));
    return f;
}
__device__ __forceinline__ u64 f2u(float2 v) { return packf2(v.x, v.y); }

// One pair-tap: lanes carry the two output pixels.
// P_c = (x_c[tap for r0], x_c[tap for r1]) per channel.
#define TAPP(P0, P1, P2, P3) do {                                         \
    u64 _s = mul2(psiP0, (P0));                                           \
    _s = fma2(psiP1, (P1), _s);                                           \
    _s = fma2(psiP2, (P2), _s);                                           \
    _s = fma2(psiP3, (P3), _s);                                           \
    float2 _f = unpack2(_s);                                              \
    u64 _E = packf2(ex2(_f.x), ex2(_f.y));                                \
    sumP = add2(sumP, _E);                                                \
    acc0 = fma2(_E, (P0), acc0);                                          \
    acc1 = fma2(_E, (P1), acc1);                                          \
    acc2 = fma2(_E, (P2), acc2);                                          \
    acc3 = fma2(_E, (P3), acc3);                                          \
} while (0)

// Load one 2-float chunk per channel at float offset `off` within the row.
#define LOADC(dst, off) do {                                              \
    dst[0] = *(const float2*)(rp + 0*PLANE + (off));                      \
    dst[1] = *(const float2*)(rp + 1*PLANE + (off));                      \
    dst[2] = *(const float2*)(rp + 2*PLANE + (off));                      \
    dst[3] = *(const float2*)(rp + 3*PLANE + (off));                      \
} while (0)

// ---------------------------------------------------------------------------
// Single fused kernel, algebraically folded:
//   score_k = psi . x_k   with  psi = (Wp^T Wt) x_p  (pre-scaled by log2 e)
//   out     = M (sum_k att_k x_k) + x,  M = Ww Wg
// Channel-major shared halo; f32x2 lanes carry the thread's 2 output pixels.
// ---------------------------------------------------------------------------
__global__ __launch_bounds__(NTHREADS) void fused_kernel(
    const float* __restrict__ x,
    const float* __restrict__ Wt,
    const float* __restrict__ Wp,
    const float* __restrict__ Wg,
    const float* __restrict__ Ww,
    float* __restrict__ out)
{
    __shared__ float xsh[4 * PLANE];   // 4 channel planes
    __shared__ float wN[16];           // N = Wp^T Wt, scaled by log2 e
    __shared__ float wM[16];           // M = Ww Wg

    int tid = threadIdx.x;

    int b  = blockIdx.z;
    int h0 = blockIdx.y * BH;
    int w0 = blockIdx.x * BW;
    const float* xb = x + b * (C * HW);

    // --- Small matrix products N, M (threads 0..31, one entry each) ---
    if (tid < 32) {
        int e = tid & 15;
        int i = e >> 2;       // row
        int j = e & 3;        // col
        if (tid < 16) {
            float s = Wp[i] * Wt[j];
            s = fmaf(Wp[4 + i],  Wt[4 + j],  s);
            s = fmaf(Wp[8 + i],  Wt[8 + j],  s);
            s = fmaf(Wp[12 + i], Wt[12 + j], s);
            wN[e] = s * 1.4426950408889634f;
        } else {
            float s = Ww[i*4 + 0] * Wg[j];
            s = fmaf(Ww[i*4 + 1], Wg[4 + j],  s);
            s = fmaf(Ww[i*4 + 2], Wg[8 + j],  s);
            s = fmaf(Ww[i*4 + 3], Wg[12 + j], s);
            wM[e] = s;
        }
    }

    // --- Halo: batch ALL global loads first (MLP), then shared stores ---
    float v0[NHIT], v1[NHIT], v2[NHIT], v3[NHIT];
    #pragma unroll
    for (int it = 0; it < NHIT; it++) {
        int idx = it * NTHREADS + tid;
        v0[it] = 0.f; v1[it] = 0.f; v2[it] = 0.f; v3[it] = 0.f;
        if (idx < NHALO) {
            int i  = idx / HALO_W;
            int j  = idx - i * HALO_W;
            int gh = h0 - PAD + i;
            int gw = w0 - PAD + j;
            if ((unsigned)gh < (unsigned)H && (unsigned)gw < (unsigned)W) {
                const float* xp = xb + gh * W + gw;
                v0[it] = xp[0];
                v1[it] = xp[HW];
                v2[it] = xp[2*HW];
                v3[it] = xp[3*HW];
            }
        }
    }
    #pragma unroll
    for (int it = 0; it < NHIT; it++) {
        int idx = it * NTHREADS + tid;
        if (idx < NHALO) {
            int i  = idx / HALO_W;
            int j  = idx - i * HALO_W;
            int o  = i * RS + j;
            xsh[0*PLANE + o] = v0[it];
            xsh[1*PLANE + o] = v1[it];
            xsh[2*PLANE + o] = v2[it];
            xsh[3*PLANE + o] = v3[it];
        }
    }

    // --- Own-pixel x loads (for psi and residual) ---
    // Lane mapping: ty = lane&1 (+2 per warp), tx = (lane>>1)&15.
    int tx = (tid >> 1) & 15;
    int ty = ((tid >> 5) << 1) | (tid & 1);
    int oh = h0 + ty;
    int ow = w0 + tx * R;
    int pixbase = oh * W + ow;

    float xs[4][R];
    #pragma unroll
    for (int c = 0; c < 4; c++) {
        float2 v = *(const float2*)(xb + c * HW + pixbase);
        xs[c][0] = v.x; xs[c][1] = v.y;
    }
    __syncthreads();

    // --- psi = N x_p, packed ACROSS THE PIXEL PAIR per channel ---
    float pr[2][4];
    #pragma unroll
    for (int r = 0; r < R; r++) {
        pr[r][0] = fmaf(wN[0],  xs[0][r], fmaf(wN[1],  xs[1][r], fmaf(wN[2],  xs[2][r], wN[3]  * xs[3][r])));
        pr[r][1] = fmaf(wN[4],  xs[0][r], fmaf(wN[5],  xs[1][r], fmaf(wN[6],  xs[2][r], wN[7]  * xs[3][r])));
        pr[r][2] = fmaf(wN[8],  xs[0][r], fmaf(wN[9],  xs[1][r], fmaf(wN[10], xs[2][r], wN[11] * xs[3][r])));
        pr[r][3] = fmaf(wN[12], xs[0][r], fmaf(wN[13], xs[1][r], fmaf(wN[14], xs[2][r], wN[15] * xs[3][r])));
    }
    u64 psiP0 = packf2(pr[0][0], pr[1][0]);
    u64 psiP1 = packf2(pr[0][1], pr[1][1]);
    u64 psiP2 = packf2(pr[0][2], pr[1][2]);
    u64 psiP3 = packf2(pr[0][3], pr[1][3]);

    u64 acc0 = 0ull, acc1 = 0ull, acc2 = 0ull, acc3 = 0ull;
    u64 sumP = 0ull;

    const float* rp = xsh + ty * RS + tx * R;

    // --- Main loop: 11 window rows; taps via overlapping float2 pairs ---
    #pragma unroll 1
    for (int ki = 0; ki < FS; ki++) {
        float2 Av[4], Bv[4], Cv[4], Dv[4], Evv[4], Fv[4];
        LOADC(Av, 0);
        LOADC(Bv, 2);
        // kj=0: (x0,x1)  kj=1: (x1,x2)  kj=2: (x2,x3)
        TAPP(f2u(Av[0]), f2u(Av[1]), f2u(Av[2]), f2u(Av[3]));
        TAPP(packf2(Av[0].y, Bv[0].x), packf2(Av[1].y, Bv[1].x),
             packf2(Av[2].y, Bv[2].x), packf2(Av[3].y, Bv[3].x));
        TAPP(f2u(Bv[0]), f2u(Bv[1]), f2u(Bv[2]), f2u(Bv[3]));
        LOADC(Cv, 4);
        LOADC(Dv, 6);
        // kj=3: (x3,x4)  kj=4: (x4,x5)  kj=5: (x5,x6)  kj=6: (x6,x7)
        TAPP(packf2(Bv[0].y, Cv[0].x), packf2(Bv[1].y, Cv[1].x),
             packf2(Bv[2].y, Cv[2].x), packf2(Bv[3].y, Cv[3].x));
        TAPP(f2u(Cv[0]), f2u(Cv[1]), f2u(Cv[2]), f2u(Cv[3]));
        TAPP(packf2(Cv[0].y, Dv[0].x), packf2(Cv[1].y, Dv[1].x),
             packf2(Cv[2].y, Dv[2].x), packf2(Cv[3].y, Dv[3].x));
        TAPP(f2u(Dv[0]), f2u(Dv[1]), f2u(Dv[2]), f2u(Dv[3]));
        LOADC(Evv, 8);
        LOADC(Fv, 10);
        // kj=7: (x7,x8)  kj=8: (x8,x9)  kj=9: (x9,x10)  kj=10: (x10,x11)
        TAPP(packf2(Dv[0].y, Evv[0].x), packf2(Dv[1].y, Evv[1].x),
             packf2(Dv[2].y, Evv[2].x), packf2(Dv[3].y, Evv[3].x));
        TAPP(f2u(Evv[0]), f2u(Evv[1]), f2u(Evv[2]), f2u(Evv[3]));
        TAPP(packf2(Evv[0].y, Fv[0].x), packf2(Evv[1].y, Fv[1].x),
             packf2(Evv[2].y, Fv[2].x), packf2(Evv[3].y, Fv[3].x));
        TAPP(f2u(Fv[0]), f2u(Fv[1]), f2u(Fv[2]), f2u(Fv[3]));
        rp += RS;
    }

    // --- Epilogue: normalize, apply M, residual; float2 stores ---
    float2 sums = unpack2(sumP);
    float inv0 = __frcp_rn(sums.x);
    float inv1 = __frcp_rn(sums.y);
    float2 f0 = unpack2(acc0);
    float2 f1 = unpack2(acc1);
    float2 f2v = unpack2(acc2);
    float2 f3 = unpack2(acc3);
    float a0[2] = { f0.x * inv0, f0.y * inv1 };
    float a1[2] = { f1.x * inv0, f1.y * inv1 };
    float a2[2] = { f2v.x * inv0, f2v.y * inv1 };
    float a3[2] = { f3.x * inv0, f3.y * inv1 };

    float* ob = out + b * (C * HW);
    #pragma unroll
    for (int c = 0; c < C; c++) {
        float2 res;
        res.x = fmaf(wM[c*4+0], a0[0], fmaf(wM[c*4+1], a1[0], fmaf(wM[c*4+2], a2[0], wM[c*4+3] * a3[0]))) + xs[c][0];
        res.y = fmaf(wM[c*4+0], a0[1], fmaf(wM[c*4+1], a1[1], fmaf(wM[c*4+2], a2[1], wM[c*4+3] * a3[1]))) + xs[c][1];
        *(float2*)(ob + c * HW + pixbase) = res;
    }
}

// ---------------------------------------------------------------------------
extern "C" void kernel_launch(void* const* d_in, const int* in_sizes, int n_in,
                              void* d_out, int out_size)
{
    const float* x  = (const float*)d_in[0];
    const float* Wt = (const float*)d_in[1];
    const float* Wp = (const float*)d_in[2];
    const float* Wg = (const float*)d_in[3];
    const float* Ww = (const float*)d_in[4];
    float* out = (float*)d_out;

    dim3 grid(W / BW, H / BH, B);
    fused_kernel<<<grid, NTHREADS>>>(x, Wt, Wp, Wg, Ww, out);
}